// round 1
// baseline (speedup 1.0000x reference)
#include <cuda_runtime.h>
#include <math.h>

// Problem constants
#define BB     64          // batch
#define TH     256         // history length
#define TR     256         // rollout length
#define KIN    1024        // input dim
#define HD     2048        // hidden dim
#define H3     6144        // 3*H
#define NSTEP  257         // 1 history step + 256 rollout steps
#define MTOT   (NSTEP*BB)  // 16448 rows of the gi GEMM

// ---------------- scratch (device globals: no allocations allowed) ----------
__device__ float g_gi[(size_t)NSTEP * BB * H3];  // 404 MB: precomputed input gates
__device__ float g_gh[BB * H3];                  // per-step hidden gates
__device__ float g_h [BB * HD];                  // current hidden state

// ---------------- packed fp32x2 FMA helpers (Blackwell FFMA2) ---------------
__device__ __forceinline__ unsigned long long pack2(float x, float y) {
    unsigned long long r;
    asm("mov.b64 %0, {%1, %2};" : "=l"(r)
        : "r"(__float_as_uint(x)), "r"(__float_as_uint(y)));
    return r;
}
__device__ __forceinline__ void ffma2(unsigned long long& acc,
                                      unsigned long long a,
                                      unsigned long long b) {
    asm("fma.rn.f32x2 %0, %1, %2, %3;" : "=l"(acc) : "l"(a), "l"(b), "l"(acc));
}
__device__ __forceinline__ float2 unpack2(unsigned long long v) {
    unsigned lo, hi;
    asm("mov.b64 {%0, %1}, %2;" : "=r"(lo), "=r"(hi) : "l"(v));
    return make_float2(__uint_as_float(lo), __uint_as_float(hi));
}

// ---------------- h init: h = history_s_list[:, TH-1, :] --------------------
__global__ __launch_bounds__(256) void hinit_kernel(const float* __restrict__ hist_s)
{
    int e = blockIdx.x * 256 + threadIdx.x;       // < BB*HD == 131072
    int b = e >> 11, j = e & (HD - 1);
    g_h[e] = hist_s[(size_t)b * TH * HD + (size_t)(TH - 1) * HD + j];
}

// ---------------- gi GEMM: [16448,1024] @ [1024,6144]^T + b_ih --------------
// BM=128, BN=64, BK=16, 256 threads, micro-tile 8m x 4n, FFMA2 paired along m.
__global__ __launch_bounds__(256) void gi_gemm(const float* __restrict__ hist_a,
                                               const float* __restrict__ a_list,
                                               const float* __restrict__ W_ih,
                                               const float* __restrict__ b_ih)
{
    __shared__ float As[16][132];   // [k][m], padded
    __shared__ float Bs[16][68];    // [k][n], padded

    const int tid   = threadIdx.x;
    const int nbase = blockIdx.x * 64;     // 96 tiles cover 6144 exactly
    const int mbase = blockIdx.y * 128;    // 129 tiles cover 16448 (+pad)

    // --- loader mapping (fixed per thread) ---
    const int kq    = tid & 3;             // which float4 in the 16-wide k strip
    const int arow0 = tid >> 2;            // rows arow0 and arow0+64
    const float* asrc[2];
    bool avalid[2];
    #pragma unroll
    for (int l = 0; l < 2; l++) {
        int row = arow0 + l * 64;
        int gm  = mbase + row;
        avalid[l] = gm < MTOT;
        int t = gm >> 6, b = gm & 63;
        if (avalid[l])
            asrc[l] = (t == 0)
                ? hist_a + (size_t)b * TH * KIN + (size_t)(TH - 1) * KIN
                : a_list + (size_t)b * TR * KIN + (size_t)(t - 1) * KIN;
        else
            asrc[l] = hist_a;              // never read (guarded)
    }
    const int bn = tid >> 2;               // 0..63
    const float* bsrc = W_ih + (size_t)(nbase + bn) * KIN;

    // --- compute mapping ---
    const int tn = tid & 15, tm = tid >> 4;
    const int m0 = tm * 8, n0 = tn * 4;

    unsigned long long acc[4][4];
    #pragma unroll
    for (int i = 0; i < 4; i++)
        #pragma unroll
        for (int j = 0; j < 4; j++) acc[i][j] = 0ULL;

    float4 va[2], vb;
    #pragma unroll
    for (int l = 0; l < 2; l++)
        va[l] = avalid[l] ? *(const float4*)(asrc[l] + kq * 4)
                          : make_float4(0.f, 0.f, 0.f, 0.f);
    vb = *(const float4*)(bsrc + kq * 4);

    for (int kt = 0; kt < KIN / 16; kt++) {
        __syncthreads();
        #pragma unroll
        for (int l = 0; l < 2; l++) {
            int row = arow0 + l * 64;
            As[kq * 4 + 0][row] = va[l].x;
            As[kq * 4 + 1][row] = va[l].y;
            As[kq * 4 + 2][row] = va[l].z;
            As[kq * 4 + 3][row] = va[l].w;
        }
        Bs[kq * 4 + 0][bn] = vb.x;
        Bs[kq * 4 + 1][bn] = vb.y;
        Bs[kq * 4 + 2][bn] = vb.z;
        Bs[kq * 4 + 3][bn] = vb.w;
        __syncthreads();

        if (kt + 1 < KIN / 16) {           // register prefetch of next tile
            int off = (kt + 1) * 16 + kq * 4;
            #pragma unroll
            for (int l = 0; l < 2; l++)
                va[l] = avalid[l] ? *(const float4*)(asrc[l] + off)
                                  : make_float4(0.f, 0.f, 0.f, 0.f);
            vb = *(const float4*)(bsrc + off);
        }

        #pragma unroll
        for (int k = 0; k < 16; k++) {
            float4 a0 = *(const float4*)&As[k][m0];
            float4 a1 = *(const float4*)&As[k][m0 + 4];
            float4 b4 = *(const float4*)&Bs[k][n0];
            unsigned long long am[4] = { pack2(a0.x, a0.y), pack2(a0.z, a0.w),
                                         pack2(a1.x, a1.y), pack2(a1.z, a1.w) };
            unsigned long long bd[4] = { pack2(b4.x, b4.x), pack2(b4.y, b4.y),
                                         pack2(b4.z, b4.z), pack2(b4.w, b4.w) };
            #pragma unroll
            for (int i = 0; i < 4; i++)
                #pragma unroll
                for (int j = 0; j < 4; j++)
                    ffma2(acc[i][j], am[i], bd[j]);
        }
    }

    #pragma unroll
    for (int i = 0; i < 4; i++) {
        int gm = mbase + m0 + 2 * i;
        if (gm >= MTOT) continue;          // valid region is 64-aligned -> pair safe
        #pragma unroll
        for (int j = 0; j < 4; j++) {
            float2 v = unpack2(acc[i][j]);
            int gn = nbase + n0 + j;
            float bias = b_ih[gn];
            g_gi[(size_t)gm * H3 + gn]       = v.x + bias;
            g_gi[(size_t)(gm + 1) * H3 + gn] = v.y + bias;
        }
    }
}

// ---------------- per-step gh GEMM: [64,2048] @ [2048,6144]^T + b_hh --------
// BM=64 (full batch), BN=42 -> 147 CTAs = one wave on 148 SMs. 224 threads,
// micro-tile 4m x 3n, FFMA2 paired along m.
__global__ __launch_bounds__(224) void gh_gemm(const float* __restrict__ W_hh,
                                               const float* __restrict__ b_hh)
{
    __shared__ float As[16][68];    // [k][m]
    __shared__ float Bs[16][43];    // [k][n]

    const int tid   = threadIdx.x;
    const int nbase = blockIdx.x * 42;

    // A: 256 float4 over 224 threads (threads 0..31 take a second one)
    const int akq  = tid & 3;
    const int arow = tid >> 2;                 // 0..55
    const bool has2 = tid < 32;
    const int idx2  = tid + 224;
    const int akq2  = idx2 & 3;
    const int arow2 = idx2 >> 2;               // 56..63

    // B: 168 float4, threads 0..167
    const bool hasB = tid < 168;
    const int bkq = tid & 3;
    const int bnr = tid >> 2;                  // 0..41
    const int gnb = nbase + bnr;
    const bool bvalid = hasB && (gnb < H3);
    const float* bsrc = W_hh + (size_t)gnb * HD;

    const int tm = tid / 14, tn = tid % 14;    // 16 m-groups x 14 n-groups
    const int m0 = tm * 4, n0 = tn * 3;

    unsigned long long acc[2][3] = {{0ULL,0ULL,0ULL},{0ULL,0ULL,0ULL}};

    float4 va  = *(const float4*)(g_h + (size_t)arow  * HD + akq  * 4);
    float4 va2 = has2 ? *(const float4*)(g_h + (size_t)arow2 * HD + akq2 * 4)
                      : make_float4(0.f,0.f,0.f,0.f);
    float4 vb  = bvalid ? *(const float4*)(bsrc + bkq * 4)
                        : make_float4(0.f,0.f,0.f,0.f);

    for (int kt = 0; kt < HD / 16; kt++) {
        __syncthreads();
        As[akq * 4 + 0][arow] = va.x;
        As[akq * 4 + 1][arow] = va.y;
        As[akq * 4 + 2][arow] = va.z;
        As[akq * 4 + 3][arow] = va.w;
        if (has2) {
            As[akq2 * 4 + 0][arow2] = va2.x;
            As[akq2 * 4 + 1][arow2] = va2.y;
            As[akq2 * 4 + 2][arow2] = va2.z;
            As[akq2 * 4 + 3][arow2] = va2.w;
        }
        if (hasB) {
            Bs[bkq * 4 + 0][bnr] = vb.x;
            Bs[bkq * 4 + 1][bnr] = vb.y;
            Bs[bkq * 4 + 2][bnr] = vb.z;
            Bs[bkq * 4 + 3][bnr] = vb.w;
        }
        __syncthreads();

        if (kt + 1 < HD / 16) {
            int off = (kt + 1) * 16;
            va = *(const float4*)(g_h + (size_t)arow * HD + off + akq * 4);
            if (has2)
                va2 = *(const float4*)(g_h + (size_t)arow2 * HD + off + akq2 * 4);
            vb = bvalid ? *(const float4*)(bsrc + off + bkq * 4)
                        : make_float4(0.f,0.f,0.f,0.f);
        }

        #pragma unroll
        for (int k = 0; k < 16; k++) {
            float4 a = *(const float4*)&As[k][m0];
            unsigned long long am[2] = { pack2(a.x, a.y), pack2(a.z, a.w) };
            float b0 = Bs[k][n0], b1 = Bs[k][n0 + 1], b2 = Bs[k][n0 + 2];
            unsigned long long bd[3] = { pack2(b0, b0), pack2(b1, b1), pack2(b2, b2) };
            #pragma unroll
            for (int i = 0; i < 2; i++)
                #pragma unroll
                for (int j = 0; j < 3; j++)
                    ffma2(acc[i][j], am[i], bd[j]);
        }
    }

    #pragma unroll
    for (int i = 0; i < 2; i++)
        #pragma unroll
        for (int j = 0; j < 3; j++) {
            int gn = nbase + n0 + j;
            if (gn < H3) {
                float2 v = unpack2(acc[i][j]);
                float bias = b_hh[gn];
                g_gh[(size_t)(m0 + 2 * i)     * H3 + gn] = v.x + bias;
                g_gh[(size_t)(m0 + 2 * i + 1) * H3 + gn] = v.y + bias;
            }
        }
}

// ---------------- gate combine + state update -------------------------------
__global__ __launch_bounds__(256) void combine_kernel(int t, float* __restrict__ out)
{
    int e = blockIdx.x * 256 + threadIdx.x;     // < BB*HD
    int b = e >> 11, j = e & (HD - 1);
    const float* gi = g_gi + (size_t)t * BB * H3 + (size_t)b * H3;
    const float* gh = g_gh + (size_t)b * H3;
    float ir = gi[j], iz = gi[j + HD], inn = gi[j + 2 * HD];
    float hr = gh[j], hz = gh[j + HD], hn  = gh[j + 2 * HD];
    float hprev = g_h[e];
    float r = 1.f / (1.f + expf(-(ir + hr)));
    float z = 1.f / (1.f + expf(-(iz + hz)));
    float n = tanhf(inn + r * hn);
    float hnew = (1.f - z) * n + z * hprev;
    g_h[e] = hnew;
    if (t >= 1)   // history step (t==0) produces no output
        out[(size_t)(BB * TR) + ((size_t)(b * TR + (t - 1))) * HD + j] = hnew;
}

// ---------------- reward: r[b,t] = sigmoid(s_list[b,t,:] . W_r + b_r) -------
__global__ __launch_bounds__(256) void reward_kernel(float* __restrict__ out,
                                                     const float* __restrict__ W_r,
                                                     const float* __restrict__ b_r)
{
    int row = blockIdx.x;                       // 0..BB*TR-1 == b*TR + t
    const float* s = out + (size_t)(BB * TR) + (size_t)row * HD;
    float acc = 0.f;
    for (int i = threadIdx.x; i < HD; i += 256)
        acc = fmaf(s[i], W_r[i], acc);
    __shared__ float red[8];
    #pragma unroll
    for (int o = 16; o > 0; o >>= 1)
        acc += __shfl_down_sync(0xffffffffu, acc, o);
    if ((threadIdx.x & 31) == 0) red[threadIdx.x >> 5] = acc;
    __syncthreads();
    if (threadIdx.x < 8) {
        float v = red[threadIdx.x];
        #pragma unroll
        for (int o = 4; o > 0; o >>= 1)
            v += __shfl_down_sync(0xffu, v, o);
        if (threadIdx.x == 0)
            out[row] = 1.f / (1.f + expf(-(v + b_r[0])));
    }
}

// ---------------- launch ----------------------------------------------------
extern "C" void kernel_launch(void* const* d_in, const int* in_sizes, int n_in,
                              void* d_out, int out_size)
{
    const float* hist_s = (const float*)d_in[0];
    const float* hist_a = (const float*)d_in[1];
    // d_in[2] = s : unused (reference never reads it)
    const float* a_list = (const float*)d_in[3];
    const float* W_ih   = (const float*)d_in[4];
    const float* W_hh   = (const float*)d_in[5];
    const float* b_ih   = (const float*)d_in[6];
    const float* b_hh   = (const float*)d_in[7];
    const float* W_r    = (const float*)d_in[8];
    const float* b_r    = (const float*)d_in[9];
    float* out = (float*)d_out;

    (void)in_sizes; (void)n_in; (void)out_size;

    hinit_kernel<<<(BB * HD) / 256, 256>>>(hist_s);
    gi_gemm<<<dim3(H3 / 64, (MTOT + 127) / 128), 256>>>(hist_a, a_list, W_ih, b_ih);

    for (int t = 0; t < NSTEP; t++) {
        gh_gemm<<<(H3 + 41) / 42, 224>>>(W_hh, b_hh);
        combine_kernel<<<(BB * HD) / 256, 256>>>(t, out);
    }

    reward_kernel<<<BB * TR, 256>>>(out, W_r, b_r);
}

// round 2
// speedup vs baseline: 1.0005x; 1.0005x over previous
#include <cuda_runtime.h>
#include <math.h>

// Problem constants
#define BB     64          // batch
#define TH     256         // history length
#define TR     256         // rollout length
#define KIN    1024        // input dim
#define HD     2048        // hidden dim
#define H3     6144        // 3*H
#define NSTEP  257         // 1 history step + 256 rollout steps
#define MTOT   (NSTEP*BB)  // 16448 rows of the gi GEMM

// ---------------- scratch (device globals: no allocations allowed) ----------
__device__ float g_gi[(size_t)NSTEP * BB * H3];  // 404 MB: precomputed input gates
__device__ float g_gh[BB * H3];                  // per-step hidden gates
__device__ float g_h [BB * HD];                  // current hidden state

// ---------------- packed fp32x2 FMA helpers (Blackwell FFMA2) ---------------
__device__ __forceinline__ unsigned long long pack2(float x, float y) {
    unsigned long long r;
    asm("mov.b64 %0, {%1, %2};" : "=l"(r)
        : "r"(__float_as_uint(x)), "r"(__float_as_uint(y)));
    return r;
}
__device__ __forceinline__ void ffma2(unsigned long long& acc,
                                      unsigned long long a,
                                      unsigned long long b) {
    asm("fma.rn.f32x2 %0, %1, %2, %3;" : "=l"(acc) : "l"(a), "l"(b), "l"(acc));
}
__device__ __forceinline__ float2 unpack2(unsigned long long v) {
    unsigned lo, hi;
    asm("mov.b64 {%0, %1}, %2;" : "=r"(lo), "=r"(hi) : "l"(v));
    return make_float2(__uint_as_float(lo), __uint_as_float(hi));
}

// ---------------- h init: h = history_s_list[:, TH-1, :] --------------------
__global__ __launch_bounds__(256) void hinit_kernel(const float* __restrict__ hist_s)
{
    int e = blockIdx.x * 256 + threadIdx.x;       // < BB*HD == 131072
    int b = e >> 11, j = e & (HD - 1);
    g_h[e] = hist_s[(size_t)b * TH * HD + (size_t)(TH - 1) * HD + j];
}

// ---------------- gi GEMM: [16448,1024] @ [1024,6144]^T + b_ih --------------
// BM=128, BN=64, BK=16, 256 threads, micro-tile 8m x 4n, FFMA2 paired along m.
__global__ __launch_bounds__(256) void gi_gemm(const float* __restrict__ hist_a,
                                               const float* __restrict__ a_list,
                                               const float* __restrict__ W_ih,
                                               const float* __restrict__ b_ih)
{
    __shared__ float As[16][132];   // [k][m], padded
    __shared__ float Bs[16][68];    // [k][n], padded

    const int tid   = threadIdx.x;
    const int nbase = blockIdx.x * 64;     // 96 tiles cover 6144 exactly
    const int mbase = blockIdx.y * 128;    // 129 tiles cover 16448 (+pad)

    // --- loader mapping (fixed per thread) ---
    const int kq    = tid & 3;             // which float4 in the 16-wide k strip
    const int arow0 = tid >> 2;            // rows arow0 and arow0+64
    const float* asrc[2];
    bool avalid[2];
    #pragma unroll
    for (int l = 0; l < 2; l++) {
        int row = arow0 + l * 64;
        int gm  = mbase + row;
        avalid[l] = gm < MTOT;
        int t = gm >> 6, b = gm & 63;
        if (avalid[l])
            asrc[l] = (t == 0)
                ? hist_a + (size_t)b * TH * KIN + (size_t)(TH - 1) * KIN
                : a_list + (size_t)b * TR * KIN + (size_t)(t - 1) * KIN;
        else
            asrc[l] = hist_a;              // never read (guarded)
    }
    const int bn = tid >> 2;               // 0..63
    const float* bsrc = W_ih + (size_t)(nbase + bn) * KIN;

    // --- compute mapping ---
    const int tn = tid & 15, tm = tid >> 4;
    const int m0 = tm * 8, n0 = tn * 4;

    unsigned long long acc[4][4];
    #pragma unroll
    for (int i = 0; i < 4; i++)
        #pragma unroll
        for (int j = 0; j < 4; j++) acc[i][j] = 0ULL;

    float4 va[2], vb;
    #pragma unroll
    for (int l = 0; l < 2; l++)
        va[l] = avalid[l] ? *(const float4*)(asrc[l] + kq * 4)
                          : make_float4(0.f, 0.f, 0.f, 0.f);
    vb = *(const float4*)(bsrc + kq * 4);

    for (int kt = 0; kt < KIN / 16; kt++) {
        __syncthreads();
        #pragma unroll
        for (int l = 0; l < 2; l++) {
            int row = arow0 + l * 64;
            As[kq * 4 + 0][row] = va[l].x;
            As[kq * 4 + 1][row] = va[l].y;
            As[kq * 4 + 2][row] = va[l].z;
            As[kq * 4 + 3][row] = va[l].w;
        }
        Bs[kq * 4 + 0][bn] = vb.x;
        Bs[kq * 4 + 1][bn] = vb.y;
        Bs[kq * 4 + 2][bn] = vb.z;
        Bs[kq * 4 + 3][bn] = vb.w;
        __syncthreads();

        if (kt + 1 < KIN / 16) {           // register prefetch of next tile
            int off = (kt + 1) * 16 + kq * 4;
            #pragma unroll
            for (int l = 0; l < 2; l++)
                va[l] = avalid[l] ? *(const float4*)(asrc[l] + off)
                                  : make_float4(0.f, 0.f, 0.f, 0.f);
            vb = *(const float4*)(bsrc + off);
        }

        #pragma unroll
        for (int k = 0; k < 16; k++) {
            float4 a0 = *(const float4*)&As[k][m0];
            float4 a1 = *(const float4*)&As[k][m0 + 4];
            float4 b4 = *(const float4*)&Bs[k][n0];
            unsigned long long am[4] = { pack2(a0.x, a0.y), pack2(a0.z, a0.w),
                                         pack2(a1.x, a1.y), pack2(a1.z, a1.w) };
            unsigned long long bd[4] = { pack2(b4.x, b4.x), pack2(b4.y, b4.y),
                                         pack2(b4.z, b4.z), pack2(b4.w, b4.w) };
            #pragma unroll
            for (int i = 0; i < 4; i++)
                #pragma unroll
                for (int j = 0; j < 4; j++)
                    ffma2(acc[i][j], am[i], bd[j]);
        }
    }

    #pragma unroll
    for (int i = 0; i < 4; i++) {
        int gm = mbase + m0 + 2 * i;
        if (gm >= MTOT) continue;          // valid region is 64-aligned -> pair safe
        #pragma unroll
        for (int j = 0; j < 4; j++) {
            float2 v = unpack2(acc[i][j]);
            int gn = nbase + n0 + j;
            float bias = b_ih[gn];
            g_gi[(size_t)gm * H3 + gn]       = v.x + bias;
            g_gi[(size_t)(gm + 1) * H3 + gn] = v.y + bias;
        }
    }
}

// ---------------- per-step gh GEMM: [64,2048] @ [2048,6144]^T + b_hh --------
// BM=64 (full batch), BN=42 -> 147 CTAs = one wave on 148 SMs. 224 threads,
// micro-tile 4m x 3n, FFMA2 paired along m.
__global__ __launch_bounds__(224) void gh_gemm(const float* __restrict__ W_hh,
                                               const float* __restrict__ b_hh)
{
    __shared__ float As[16][68];    // [k][m]
    __shared__ float Bs[16][43];    // [k][n]

    const int tid   = threadIdx.x;
    const int nbase = blockIdx.x * 42;

    // A: 256 float4 over 224 threads (threads 0..31 take a second one)
    const int akq  = tid & 3;
    const int arow = tid >> 2;                 // 0..55
    const bool has2 = tid < 32;
    const int idx2  = tid + 224;
    const int akq2  = idx2 & 3;
    const int arow2 = idx2 >> 2;               // 56..63

    // B: 168 float4, threads 0..167
    const bool hasB = tid < 168;
    const int bkq = tid & 3;
    const int bnr = tid >> 2;                  // 0..41
    const int gnb = nbase + bnr;
    const bool bvalid = hasB && (gnb < H3);
    const float* bsrc = W_hh + (size_t)gnb * HD;

    const int tm = tid / 14, tn = tid % 14;    // 16 m-groups x 14 n-groups
    const int m0 = tm * 4, n0 = tn * 3;

    unsigned long long acc[2][3] = {{0ULL,0ULL,0ULL},{0ULL,0ULL,0ULL}};

    float4 va  = *(const float4*)(g_h + (size_t)arow  * HD + akq  * 4);
    float4 va2 = has2 ? *(const float4*)(g_h + (size_t)arow2 * HD + akq2 * 4)
                      : make_float4(0.f,0.f,0.f,0.f);
    float4 vb  = bvalid ? *(const float4*)(bsrc + bkq * 4)
                        : make_float4(0.f,0.f,0.f,0.f);

    for (int kt = 0; kt < HD / 16; kt++) {
        __syncthreads();
        As[akq * 4 + 0][arow] = va.x;
        As[akq * 4 + 1][arow] = va.y;
        As[akq * 4 + 2][arow] = va.z;
        As[akq * 4 + 3][arow] = va.w;
        if (has2) {
            As[akq2 * 4 + 0][arow2] = va2.x;
            As[akq2 * 4 + 1][arow2] = va2.y;
            As[akq2 * 4 + 2][arow2] = va2.z;
            As[akq2 * 4 + 3][arow2] = va2.w;
        }
        if (hasB) {
            Bs[bkq * 4 + 0][bnr] = vb.x;
            Bs[bkq * 4 + 1][bnr] = vb.y;
            Bs[bkq * 4 + 2][bnr] = vb.z;
            Bs[bkq * 4 + 3][bnr] = vb.w;
        }
        __syncthreads();

        if (kt + 1 < HD / 16) {
            int off = (kt + 1) * 16;
            va = *(const float4*)(g_h + (size_t)arow * HD + off + akq * 4);
            if (has2)
                va2 = *(const float4*)(g_h + (size_t)arow2 * HD + off + akq2 * 4);
            vb = bvalid ? *(const float4*)(bsrc + off + bkq * 4)
                        : make_float4(0.f,0.f,0.f,0.f);
        }

        #pragma unroll
        for (int k = 0; k < 16; k++) {
            float4 a = *(const float4*)&As[k][m0];
            unsigned long long am[2] = { pack2(a.x, a.y), pack2(a.z, a.w) };
            float b0 = Bs[k][n0], b1 = Bs[k][n0 + 1], b2 = Bs[k][n0 + 2];
            unsigned long long bd[3] = { pack2(b0, b0), pack2(b1, b1), pack2(b2, b2) };
            #pragma unroll
            for (int i = 0; i < 2; i++)
                #pragma unroll
                for (int j = 0; j < 3; j++)
                    ffma2(acc[i][j], am[i], bd[j]);
        }
    }

    #pragma unroll
    for (int i = 0; i < 2; i++)
        #pragma unroll
        for (int j = 0; j < 3; j++) {
            int gn = nbase + n0 + j;
            if (gn < H3) {
                float2 v = unpack2(acc[i][j]);
                float bias = b_hh[gn];
                g_gh[(size_t)(m0 + 2 * i)     * H3 + gn] = v.x + bias;
                g_gh[(size_t)(m0 + 2 * i + 1) * H3 + gn] = v.y + bias;
            }
        }
}

// ---------------- gate combine + state update -------------------------------
__global__ __launch_bounds__(256) void combine_kernel(int t, float* __restrict__ out)
{
    int e = blockIdx.x * 256 + threadIdx.x;     // < BB*HD
    int b = e >> 11, j = e & (HD - 1);
    const float* gi = g_gi + (size_t)t * BB * H3 + (size_t)b * H3;
    const float* gh = g_gh + (size_t)b * H3;
    float ir = gi[j], iz = gi[j + HD], inn = gi[j + 2 * HD];
    float hr = gh[j], hz = gh[j + HD], hn  = gh[j + 2 * HD];
    float hprev = g_h[e];
    float r = 1.f / (1.f + expf(-(ir + hr)));
    float z = 1.f / (1.f + expf(-(iz + hz)));
    float n = tanhf(inn + r * hn);
    float hnew = (1.f - z) * n + z * hprev;
    g_h[e] = hnew;
    if (t >= 1)   // history step (t==0) produces no output
        out[(size_t)(BB * TR) + ((size_t)(b * TR + (t - 1))) * HD + j] = hnew;
}

// ---------------- reward: r[b,t] = sigmoid(s_list[b,t,:] . W_r + b_r) -------
__global__ __launch_bounds__(256) void reward_kernel(float* __restrict__ out,
                                                     const float* __restrict__ W_r,
                                                     const float* __restrict__ b_r)
{
    int row = blockIdx.x;                       // 0..BB*TR-1 == b*TR + t
    const float* s = out + (size_t)(BB * TR) + (size_t)row * HD;
    float acc = 0.f;
    for (int i = threadIdx.x; i < HD; i += 256)
        acc = fmaf(s[i], W_r[i], acc);
    __shared__ float red[8];
    #pragma unroll
    for (int o = 16; o > 0; o >>= 1)
        acc += __shfl_down_sync(0xffffffffu, acc, o);
    if ((threadIdx.x & 31) == 0) red[threadIdx.x >> 5] = acc;
    __syncthreads();
    if (threadIdx.x < 8) {
        float v = red[threadIdx.x];
        #pragma unroll
        for (int o = 4; o > 0; o >>= 1)
            v += __shfl_down_sync(0xffu, v, o);
        if (threadIdx.x == 0)
            out[row] = 1.f / (1.f + expf(-(v + b_r[0])));
    }
}

// ---------------- launch ----------------------------------------------------
extern "C" void kernel_launch(void* const* d_in, const int* in_sizes, int n_in,
                              void* d_out, int out_size)
{
    const float* hist_s = (const float*)d_in[0];
    const float* hist_a = (const float*)d_in[1];
    // d_in[2] = s : unused (reference never reads it)
    const float* a_list = (const float*)d_in[3];
    const float* W_ih   = (const float*)d_in[4];
    const float* W_hh   = (const float*)d_in[5];
    const float* b_ih   = (const float*)d_in[6];
    const float* b_hh   = (const float*)d_in[7];
    const float* W_r    = (const float*)d_in[8];
    const float* b_r    = (const float*)d_in[9];
    float* out = (float*)d_out;

    (void)in_sizes; (void)n_in; (void)out_size;

    hinit_kernel<<<(BB * HD) / 256, 256>>>(hist_s);
    gi_gemm<<<dim3(H3 / 64, (MTOT + 127) / 128), 256>>>(hist_a, a_list, W_ih, b_ih);

    for (int t = 0; t < NSTEP; t++) {
        gh_gemm<<<(H3 + 41) / 42, 224>>>(W_hh, b_hh);
        combine_kernel<<<(BB * HD) / 256, 256>>>(t, out);
    }

    reward_kernel<<<BB * TR, 256>>>(out, W_r, b_r);
}